// round 13
// baseline (speedup 1.0000x reference)
#include <cuda_runtime.h>
#include <cstdint>

#define BATCH   8
#define CIN     256
#define HWPX    4096
#define WIDTH   64
#define CR      64
#define GROUPS  32
#define GCH     8

// intermediate y = relu6(bn(conv1(x)))  : [B][64][4096] = 8.4 MB (L2-resident)
__device__ __align__(16) float g_y[(size_t)BATCH * CR * HWPX];

typedef unsigned long long u64;

// ---------------- packed f32x2 helpers ----------------
__device__ __forceinline__ u64 ffma2(u64 a, u64 b, u64 c) {
    u64 d;
    asm("fma.rn.f32x2 %0, %1, %2, %3;" : "=l"(d) : "l"(a), "l"(b), "l"(c));
    return d;
}
__device__ __forceinline__ u64 pack2(float lo, float hi) {
    u64 d;
    asm("mov.b64 %0, {%1, %2};" : "=l"(d) : "f"(lo), "f"(hi));
    return d;
}
__device__ __forceinline__ float2 unpack2(u64 v) {
    float2 r;
    asm("mov.b64 {%0, %1}, %2;" : "=f"(r.x), "=f"(r.y) : "l"(v));
    return r;
}

// ---------------------------------------------------------------------------
// K1: conv1 (256->64) + BN + ReLU6 -> g_y
// grid (64 px-tiles of 64, 8 batch) = 512 CTAs, 128 threads, 3 CTAs/SM
//   -> 3.46 CTAs/SM average: kills the 2-wave imbalance of the 256-CTA shape.
// smem: w1t [256ci][64co] transposed (64KB)
// thread: 1 quad (4px) x 8 co; per iter: 1 LDG.128 + 2 LDS.128 + 4 packs + 16 FFMA2
// ---------------------------------------------------------------------------
__global__ void __launch_bounds__(128, 3)
k1_conv1(const float* __restrict__ x,
         const float* __restrict__ w1, const float* __restrict__ b1,
         const float* __restrict__ gma, const float* __restrict__ bta,
         const float* __restrict__ mu,  const float* __restrict__ var)
{
    extern __shared__ float w1t[];                                     // [256][64]
    const ulonglong2* w1tv = reinterpret_cast<const ulonglong2*>(w1t); // [256][16]

    const int tid  = threadIdx.x;
    const int quad = tid & 15;         // px quad (16 quads = 64 px)
    const int cg   = tid >> 4;         // co group 0..7 (8 co each)
    const int b    = blockIdx.y;
    const int px0  = blockIdx.x * 64;

    // stage w1 transposed: w1t[ci][co] = w1[co][ci]  (128 threads)
    #pragma unroll 8
    for (int k = 0; k < 128; ++k) {
        int i  = tid + k * 128;
        int co = i & 63, ci = i >> 6;
        w1t[ci * 64 + co] = w1[co * 256 + ci];
    }
    __syncthreads();

    u64 acc[4][4];
    #pragma unroll
    for (int k = 0; k < 4; ++k)
        #pragma unroll
        for (int j = 0; j < 4; ++j) acc[k][j] = 0ull;

    const float4* x4 = reinterpret_cast<const float4*>(x + (size_t)b * CIN * HWPX + px0) + quad;

    float4 xv = x4[0];
    #pragma unroll 4
    for (int ci = 0; ci < 256; ++ci) {
        float4 xn = (ci < 255) ? x4[(ci + 1) * (HWPX / 4)] : xv;
        ulonglong2 wv0 = w1tv[ci * 16 + cg * 2];       // co pairs {0,1},{2,3}
        ulonglong2 wv1 = w1tv[ci * 16 + cg * 2 + 1];   // co pairs {4,5},{6,7}
        u64 xx0 = pack2(xv.x, xv.x);
        u64 xx1 = pack2(xv.y, xv.y);
        u64 xx2 = pack2(xv.z, xv.z);
        u64 xx3 = pack2(xv.w, xv.w);
        acc[0][0] = ffma2(wv0.x, xx0, acc[0][0]);
        acc[0][1] = ffma2(wv0.x, xx1, acc[0][1]);
        acc[0][2] = ffma2(wv0.x, xx2, acc[0][2]);
        acc[0][3] = ffma2(wv0.x, xx3, acc[0][3]);
        acc[1][0] = ffma2(wv0.y, xx0, acc[1][0]);
        acc[1][1] = ffma2(wv0.y, xx1, acc[1][1]);
        acc[1][2] = ffma2(wv0.y, xx2, acc[1][2]);
        acc[1][3] = ffma2(wv0.y, xx3, acc[1][3]);
        acc[2][0] = ffma2(wv1.x, xx0, acc[2][0]);
        acc[2][1] = ffma2(wv1.x, xx1, acc[2][1]);
        acc[2][2] = ffma2(wv1.x, xx2, acc[2][2]);
        acc[2][3] = ffma2(wv1.x, xx3, acc[2][3]);
        acc[3][0] = ffma2(wv1.y, xx0, acc[3][0]);
        acc[3][1] = ffma2(wv1.y, xx1, acc[3][1]);
        acc[3][2] = ffma2(wv1.y, xx2, acc[3][2]);
        acc[3][3] = ffma2(wv1.y, xx3, acc[3][3]);
        xv = xn;
    }

    float4* y4 = reinterpret_cast<float4*>(g_y + (size_t)b * CR * HWPX + px0) + quad;
    #pragma unroll
    for (int k = 0; k < 4; ++k) {
        int co0 = cg * 8 + 2 * k, co1 = co0 + 1;
        float s0  = __ldg(&gma[co0]) * rsqrtf(__ldg(&var[co0]) + 1e-5f);
        float bb0 = fmaf(__ldg(&b1[co0]), s0, __ldg(&bta[co0]) - __ldg(&mu[co0]) * s0);
        float s1  = __ldg(&gma[co1]) * rsqrtf(__ldg(&var[co1]) + 1e-5f);
        float bb1 = fmaf(__ldg(&b1[co1]), s1, __ldg(&bta[co1]) - __ldg(&mu[co1]) * s1);
        float4 r0, r1;
        float* r0f = reinterpret_cast<float*>(&r0);
        float* r1f = reinterpret_cast<float*>(&r1);
        #pragma unroll
        for (int j = 0; j < 4; ++j) {
            float2 f = unpack2(acc[k][j]);
            r0f[j] = fminf(fmaxf(fmaf(f.x, s0, bb0), 0.f), 6.f);
            r1f[j] = fminf(fmaxf(fmaf(f.y, s1, bb1), 0.f), 6.f);
        }
        y4[(size_t)co0 * (HWPX / 4)] = r0;
        y4[(size_t)co1 * (HWPX / 4)] = r1;
    }
}

// ---------------------------------------------------------------------------
// K2: fused conv2 + involution, single pass, DENSE 13-slot tap pairs
// (round-12 verbatim: measured 117.4us)
// ---------------------------------------------------------------------------
__global__ void __launch_bounds__(256, 2)
k2_fused(const float* __restrict__ x,
         const float* __restrict__ w2, const float* __restrict__ b2,
         float* __restrict__ out)
{
    extern __shared__ char smraw[];
    float* xh  = reinterpret_cast<float*>(smraw);                 // 27648 B
    float* w2p = reinterpret_cast<float*>(smraw + 27648);         // 7168 B

    const int tid = threadIdx.x;
    const int b   = blockIdx.z;
    const int g   = blockIdx.y;
    const int h0  = blockIdx.x * 8;
    const int px0 = h0 * WIDTH;
    const int rr  = tid >> 5;        // tile row 0..7
    const int col = (tid & 31) * 2;  // first column of the pair

    // ---- stage x halo: 8 ch x 12 rows x 68 cols, pitch 72 ----
    const float* xb = x + ((size_t)b * CIN + g * GCH) * HWPX;
    for (int i = tid; i < 8 * 12 * 68; i += 256) {
        int c   = i / 816;
        int rem = i - c * 816;
        int r2  = rem / 68;
        int cc  = rem - r2 * 68;
        int hy = h0 - 2 + r2, wx = cc - 2;
        float v = 0.f;
        if ((unsigned)hy < 64u && (unsigned)wx < 64u)
            v = xb[c * HWPX + hy * WIDTH + wx];
        xh[c * 864 + r2 * 72 + cc] = v;
    }
    // ---- stage w2p[cr][t] = w2[(g*25+t)*64+cr], t=25..27 pad 0 ----
    for (int i = tid; i < 64 * 28; i += 256) {
        int cr = i / 28, t = i - cr * 28;
        float v = (t < 25) ? w2[(size_t)(g * 25 + t) * 64 + cr] : 0.f;
        w2p[cr * 28 + t] = v;
    }
    __syncthreads();

    // ---- ka[m] = {taps 2m, 2m+1}, seeded with bias (tap25 -> 0) ----
    u64 kaA[13], kaB[13];
    #pragma unroll
    for (int m = 0; m < 13; ++m) {
        float e = __ldg(b2 + g * 25 + 2 * m);
        float o = (2 * m + 1 < 25) ? __ldg(b2 + g * 25 + 2 * m + 1) : 0.f;
        kaA[m] = pack2(e, o);
        kaB[m] = kaA[m];
    }

    // ---- conv2: single pass over 64 reduced channels ----
    const u64* yp = reinterpret_cast<const u64*>(g_y + (size_t)b * CR * HWPX + px0) + tid;
    u64 ybuf[4];
    #pragma unroll
    for (int i = 0; i < 4; ++i) ybuf[i] = yp[(size_t)i * (HWPX / 2)];

    #pragma unroll 4
    for (int cr = 0; cr < 64; ++cr) {
        u64 yv = ybuf[cr & 3];
        if (cr < 60) ybuf[cr & 3] = yp[(size_t)(cr + 4) * (HWPX / 2)];
        float2 yf = unpack2(yv);
        u64 y00 = pack2(yf.x, yf.x);
        u64 y11 = pack2(yf.y, yf.y);

        const ulonglong2* wr = reinterpret_cast<const ulonglong2*>(w2p + cr * 28);
        ulonglong2 wv[7];
        #pragma unroll
        for (int m = 0; m < 7; ++m) wv[m] = wr[m];

        #pragma unroll
        for (int m = 0; m < 13; ++m) {
            u64 w = (m & 1) ? wv[m >> 1].y : wv[m >> 1].x;   // {w2[2m], w2[2m+1]}
            kaA[m] = ffma2(w, y00, kaA[m]);
            kaB[m] = ffma2(w, y11, kaB[m]);
        }
    }

    // ---- involution + store: rolling 2-row window, slots cross rows ----
    #pragma unroll
    for (int c = 0; c < 8; ++c) {
        const float* xc = xh + c * 864 + rr * 72 + col;
        float2 a0, a1, a2, b0, b1, b2v;
        {   const float2* r0 = reinterpret_cast<const float2*>(xc);
            a0 = r0[0]; a1 = r0[1]; a2 = r0[2]; }
        {   const float2* r1 = reinterpret_cast<const float2*>(xc + 72);
            b0 = r1[0]; b1 = r1[1]; b2v = r1[2]; }

        u64 oA = 0ull, oB = 0ull;
        oA = ffma2(kaA[0], pack2(a0.x, a0.y), oA);
        oB = ffma2(kaB[0], pack2(a0.y, a1.x), oB);
        oA = ffma2(kaA[1], pack2(a1.x, a1.y), oA);
        oB = ffma2(kaB[1], pack2(a1.y, a2.x), oB);
        oA = ffma2(kaA[2], pack2(a2.x, b0.x), oA);
        oB = ffma2(kaB[2], pack2(a2.y, b0.y), oB);
        {   const float2* r2 = reinterpret_cast<const float2*>(xc + 144);
            a0 = r2[0]; a1 = r2[1]; a2 = r2[2]; }
        oA = ffma2(kaA[3], pack2(b0.y, b1.x), oA);
        oB = ffma2(kaB[3], pack2(b1.x, b1.y), oB);
        oA = ffma2(kaA[4], pack2(b1.y, b2v.x), oA);
        oB = ffma2(kaB[4], pack2(b2v.x, b2v.y), oB);
        oA = ffma2(kaA[5], pack2(a0.x, a0.y), oA);
        oB = ffma2(kaB[5], pack2(a0.y, a1.x), oB);
        oA = ffma2(kaA[6], pack2(a1.x, a1.y), oA);
        oB = ffma2(kaB[6], pack2(a1.y, a2.x), oB);
        {   const float2* r3 = reinterpret_cast<const float2*>(xc + 216);
            b0 = r3[0]; b1 = r3[1]; b2v = r3[2]; }
        oA = ffma2(kaA[7], pack2(a2.x, b0.x), oA);
        oB = ffma2(kaB[7], pack2(a2.y, b0.y), oB);
        oA = ffma2(kaA[8], pack2(b0.y, b1.x), oA);
        oB = ffma2(kaB[8], pack2(b1.x, b1.y), oB);
        oA = ffma2(kaA[9], pack2(b1.y, b2v.x), oA);
        oB = ffma2(kaB[9], pack2(b2v.x, b2v.y), oB);
        {   const float2* r4 = reinterpret_cast<const float2*>(xc + 288);
            a0 = r4[0]; a1 = r4[1]; a2 = r4[2]; }
        oA = ffma2(kaA[10], pack2(a0.x, a0.y), oA);
        oB = ffma2(kaB[10], pack2(a0.y, a1.x), oB);
        oA = ffma2(kaA[11], pack2(a1.x, a1.y), oA);
        oB = ffma2(kaB[11], pack2(a1.y, a2.x), oB);
        oA = ffma2(kaA[12], pack2(a2.x, a2.x), oA);
        oB = ffma2(kaB[12], pack2(a2.y, a2.y), oB);

        float2 fa = unpack2(oA);
        float2 fb = unpack2(oB);
        float2 rv;
        rv.x = fa.x + fa.y;
        rv.y = fb.x + fb.y;
        *reinterpret_cast<float2*>(
            out + ((size_t)b * CIN + g * GCH + c) * HWPX + px0 + rr * WIDTH + col) = rv;
    }
}

// ---------------------------------------------------------------------------
extern "C" void kernel_launch(void* const* d_in, const int* in_sizes, int n_in,
                              void* d_out, int out_size)
{
    const float* x   = (const float*)d_in[0];
    const float* w1  = (const float*)d_in[1];
    const float* b1  = (const float*)d_in[2];
    const float* gma = (const float*)d_in[3];
    const float* bta = (const float*)d_in[4];
    const float* mu  = (const float*)d_in[5];
    const float* var = (const float*)d_in[6];
    const float* w2  = (const float*)d_in[7];
    const float* b2  = (const float*)d_in[8];
    float* out = (float*)d_out;

    const int SMEM1 = 65536;          // w1t
    const int SMEM2 = 27648 + 7168;   // 34816 B
    cudaFuncSetAttribute(k1_conv1, cudaFuncAttributeMaxDynamicSharedMemorySize, SMEM1);
    cudaFuncSetAttribute(k2_fused, cudaFuncAttributeMaxDynamicSharedMemorySize, SMEM2);

    k1_conv1<<<dim3(64, 8), 128, SMEM1>>>(x, w1, b1, gma, bta, mu, var);
    k2_fused<<<dim3(8, 32, 8), 256, SMEM2>>>(x, w2, b2, out);
}

// round 14
// speedup vs baseline: 1.2278x; 1.2278x over previous
#include <cuda_runtime.h>
#include <cstdint>

#define BATCH   8
#define CIN     256
#define HWPX    4096
#define WIDTH   64
#define CR      64
#define GROUPS  32
#define GCH     8

// intermediate y = relu6(bn(conv1(x)))  : [B][64][4096] = 8.4 MB (L2-resident)
__device__ __align__(16) float g_y[(size_t)BATCH * CR * HWPX];

typedef unsigned long long u64;

// ---------------- packed f32x2 helpers ----------------
__device__ __forceinline__ u64 ffma2(u64 a, u64 b, u64 c) {
    u64 d;
    asm("fma.rn.f32x2 %0, %1, %2, %3;" : "=l"(d) : "l"(a), "l"(b), "l"(c));
    return d;
}
__device__ __forceinline__ u64 pack2(float lo, float hi) {
    u64 d;
    asm("mov.b64 %0, {%1, %2};" : "=l"(d) : "f"(lo), "f"(hi));
    return d;
}
__device__ __forceinline__ float2 unpack2(u64 v) {
    float2 r;
    asm("mov.b64 {%0, %1}, %2;" : "=f"(r.x), "=f"(r.y) : "l"(v));
    return r;
}

// ---------------------------------------------------------------------------
// K1: conv1 (256->64) + BN + ReLU6 -> g_y   (round-11 verbatim: 37us measured)
// grid (32 px-tiles of 128, 8 batch) = 256 CTAs, 256 threads, 3 CTAs/SM
// smem: w1t [256ci][64co] transposed (64KB)
// warp = 32 lanes x float4 = fully-coalesced 512B LDG per channel
// thread: 1 quad x 8 co (acc 4x4 u64), lookahead-1 on x
// ---------------------------------------------------------------------------
__global__ void __launch_bounds__(256, 3)
k1_conv1(const float* __restrict__ x,
         const float* __restrict__ w1, const float* __restrict__ b1,
         const float* __restrict__ gma, const float* __restrict__ bta,
         const float* __restrict__ mu,  const float* __restrict__ var)
{
    extern __shared__ float w1t[];                                     // [256][64]
    const ulonglong2* w1tv = reinterpret_cast<const ulonglong2*>(w1t); // [256][16]

    const int tid  = threadIdx.x;
    const int lane = tid & 31;         // px quad (32 quads = 128 px)
    const int cg   = tid >> 5;         // co group: 8 co
    const int b    = blockIdx.y;
    const int px0  = blockIdx.x * 128;

    #pragma unroll 8
    for (int k = 0; k < 64; ++k) {
        int i  = tid + k * 256;
        int co = i & 63, ci = i >> 6;
        w1t[ci * 64 + co] = w1[co * 256 + ci];
    }
    __syncthreads();

    u64 acc[4][4];
    #pragma unroll
    for (int k = 0; k < 4; ++k)
        #pragma unroll
        for (int j = 0; j < 4; ++j) acc[k][j] = 0ull;

    const float4* x4 = reinterpret_cast<const float4*>(x + (size_t)b * CIN * HWPX + px0) + lane;

    float4 xv = x4[0];
    #pragma unroll 4
    for (int ci = 0; ci < 256; ++ci) {
        float4 xn = (ci < 255) ? x4[(ci + 1) * (HWPX / 4)] : xv;
        ulonglong2 wv0 = w1tv[ci * 16 + cg * 2];       // co pairs {0,1},{2,3}
        ulonglong2 wv1 = w1tv[ci * 16 + cg * 2 + 1];   // co pairs {4,5},{6,7}
        u64 xx0 = pack2(xv.x, xv.x);
        u64 xx1 = pack2(xv.y, xv.y);
        u64 xx2 = pack2(xv.z, xv.z);
        u64 xx3 = pack2(xv.w, xv.w);
        acc[0][0] = ffma2(wv0.x, xx0, acc[0][0]);
        acc[0][1] = ffma2(wv0.x, xx1, acc[0][1]);
        acc[0][2] = ffma2(wv0.x, xx2, acc[0][2]);
        acc[0][3] = ffma2(wv0.x, xx3, acc[0][3]);
        acc[1][0] = ffma2(wv0.y, xx0, acc[1][0]);
        acc[1][1] = ffma2(wv0.y, xx1, acc[1][1]);
        acc[1][2] = ffma2(wv0.y, xx2, acc[1][2]);
        acc[1][3] = ffma2(wv0.y, xx3, acc[1][3]);
        acc[2][0] = ffma2(wv1.x, xx0, acc[2][0]);
        acc[2][1] = ffma2(wv1.x, xx1, acc[2][1]);
        acc[2][2] = ffma2(wv1.x, xx2, acc[2][2]);
        acc[2][3] = ffma2(wv1.x, xx3, acc[2][3]);
        acc[3][0] = ffma2(wv1.y, xx0, acc[3][0]);
        acc[3][1] = ffma2(wv1.y, xx1, acc[3][1]);
        acc[3][2] = ffma2(wv1.y, xx2, acc[3][2]);
        acc[3][3] = ffma2(wv1.y, xx3, acc[3][3]);
        xv = xn;
    }

    float4* y4 = reinterpret_cast<float4*>(g_y + (size_t)b * CR * HWPX + px0) + lane;
    #pragma unroll
    for (int k = 0; k < 4; ++k) {
        int co0 = cg * 8 + 2 * k, co1 = co0 + 1;
        float s0  = __ldg(&gma[co0]) * rsqrtf(__ldg(&var[co0]) + 1e-5f);
        float bb0 = fmaf(__ldg(&b1[co0]), s0, __ldg(&bta[co0]) - __ldg(&mu[co0]) * s0);
        float s1  = __ldg(&gma[co1]) * rsqrtf(__ldg(&var[co1]) + 1e-5f);
        float bb1 = fmaf(__ldg(&b1[co1]), s1, __ldg(&bta[co1]) - __ldg(&mu[co1]) * s1);
        float4 r0, r1;
        float* r0f = reinterpret_cast<float*>(&r0);
        float* r1f = reinterpret_cast<float*>(&r1);
        #pragma unroll
        for (int j = 0; j < 4; ++j) {
            float2 f = unpack2(acc[k][j]);
            r0f[j] = fminf(fmaxf(fmaf(f.x, s0, bb0), 0.f), 6.f);
            r1f[j] = fminf(fmaxf(fmaf(f.y, s1, bb1), 0.f), 6.f);
        }
        y4[(size_t)co0 * (HWPX / 4)] = r0;
        y4[(size_t)co1 * (HWPX / 4)] = r1;
    }
}

// ---------------------------------------------------------------------------
// K2: fused conv2 + involution, single pass, DENSE 13-slot tap pairs
// (round-12 verbatim: 117.3us measured)
// ---------------------------------------------------------------------------
__global__ void __launch_bounds__(256, 2)
k2_fused(const float* __restrict__ x,
         const float* __restrict__ w2, const float* __restrict__ b2,
         float* __restrict__ out)
{
    extern __shared__ char smraw[];
    float* xh  = reinterpret_cast<float*>(smraw);                 // 27648 B
    float* w2p = reinterpret_cast<float*>(smraw + 27648);         // 7168 B

    const int tid = threadIdx.x;
    const int b   = blockIdx.z;
    const int g   = blockIdx.y;
    const int h0  = blockIdx.x * 8;
    const int px0 = h0 * WIDTH;
    const int rr  = tid >> 5;        // tile row 0..7
    const int col = (tid & 31) * 2;  // first column of the pair

    // ---- stage x halo: 8 ch x 12 rows x 68 cols, pitch 72 ----
    const float* xb = x + ((size_t)b * CIN + g * GCH) * HWPX;
    for (int i = tid; i < 8 * 12 * 68; i += 256) {
        int c   = i / 816;
        int rem = i - c * 816;
        int r2  = rem / 68;
        int cc  = rem - r2 * 68;
        int hy = h0 - 2 + r2, wx = cc - 2;
        float v = 0.f;
        if ((unsigned)hy < 64u && (unsigned)wx < 64u)
            v = xb[c * HWPX + hy * WIDTH + wx];
        xh[c * 864 + r2 * 72 + cc] = v;
    }
    // ---- stage w2p[cr][t] = w2[(g*25+t)*64+cr], t=25..27 pad 0 ----
    for (int i = tid; i < 64 * 28; i += 256) {
        int cr = i / 28, t = i - cr * 28;
        float v = (t < 25) ? w2[(size_t)(g * 25 + t) * 64 + cr] : 0.f;
        w2p[cr * 28 + t] = v;
    }
    __syncthreads();

    // ---- ka[m] = {taps 2m, 2m+1}, seeded with bias (tap25 -> 0) ----
    u64 kaA[13], kaB[13];
    #pragma unroll
    for (int m = 0; m < 13; ++m) {
        float e = __ldg(b2 + g * 25 + 2 * m);
        float o = (2 * m + 1 < 25) ? __ldg(b2 + g * 25 + 2 * m + 1) : 0.f;
        kaA[m] = pack2(e, o);
        kaB[m] = kaA[m];
    }

    // ---- conv2: single pass over 64 reduced channels ----
    const u64* yp = reinterpret_cast<const u64*>(g_y + (size_t)b * CR * HWPX + px0) + tid;
    u64 ybuf[4];
    #pragma unroll
    for (int i = 0; i < 4; ++i) ybuf[i] = yp[(size_t)i * (HWPX / 2)];

    #pragma unroll 4
    for (int cr = 0; cr < 64; ++cr) {
        u64 yv = ybuf[cr & 3];
        if (cr < 60) ybuf[cr & 3] = yp[(size_t)(cr + 4) * (HWPX / 2)];
        float2 yf = unpack2(yv);
        u64 y00 = pack2(yf.x, yf.x);
        u64 y11 = pack2(yf.y, yf.y);

        const ulonglong2* wr = reinterpret_cast<const ulonglong2*>(w2p + cr * 28);
        ulonglong2 wv[7];
        #pragma unroll
        for (int m = 0; m < 7; ++m) wv[m] = wr[m];

        #pragma unroll
        for (int m = 0; m < 13; ++m) {
            u64 w = (m & 1) ? wv[m >> 1].y : wv[m >> 1].x;   // {w2[2m], w2[2m+1]}
            kaA[m] = ffma2(w, y00, kaA[m]);
            kaB[m] = ffma2(w, y11, kaB[m]);
        }
    }

    // ---- involution + store: rolling 2-row window, slots cross rows ----
    #pragma unroll
    for (int c = 0; c < 8; ++c) {
        const float* xc = xh + c * 864 + rr * 72 + col;
        float2 a0, a1, a2, b0, b1, b2v;
        {   const float2* r0 = reinterpret_cast<const float2*>(xc);
            a0 = r0[0]; a1 = r0[1]; a2 = r0[2]; }
        {   const float2* r1 = reinterpret_cast<const float2*>(xc + 72);
            b0 = r1[0]; b1 = r1[1]; b2v = r1[2]; }

        u64 oA = 0ull, oB = 0ull;
        oA = ffma2(kaA[0], pack2(a0.x, a0.y), oA);
        oB = ffma2(kaB[0], pack2(a0.y, a1.x), oB);
        oA = ffma2(kaA[1], pack2(a1.x, a1.y), oA);
        oB = ffma2(kaB[1], pack2(a1.y, a2.x), oB);
        oA = ffma2(kaA[2], pack2(a2.x, b0.x), oA);
        oB = ffma2(kaB[2], pack2(a2.y, b0.y), oB);
        {   const float2* r2 = reinterpret_cast<const float2*>(xc + 144);
            a0 = r2[0]; a1 = r2[1]; a2 = r2[2]; }
        oA = ffma2(kaA[3], pack2(b0.y, b1.x), oA);
        oB = ffma2(kaB[3], pack2(b1.x, b1.y), oB);
        oA = ffma2(kaA[4], pack2(b1.y, b2v.x), oA);
        oB = ffma2(kaB[4], pack2(b2v.x, b2v.y), oB);
        oA = ffma2(kaA[5], pack2(a0.x, a0.y), oA);
        oB = ffma2(kaB[5], pack2(a0.y, a1.x), oB);
        oA = ffma2(kaA[6], pack2(a1.x, a1.y), oA);
        oB = ffma2(kaB[6], pack2(a1.y, a2.x), oB);
        {   const float2* r3 = reinterpret_cast<const float2*>(xc + 216);
            b0 = r3[0]; b1 = r3[1]; b2v = r3[2]; }
        oA = ffma2(kaA[7], pack2(a2.x, b0.x), oA);
        oB = ffma2(kaB[7], pack2(a2.y, b0.y), oB);
        oA = ffma2(kaA[8], pack2(b0.y, b1.x), oA);
        oB = ffma2(kaB[8], pack2(b1.x, b1.y), oB);
        oA = ffma2(kaA[9], pack2(b1.y, b2v.x), oA);
        oB = ffma2(kaB[9], pack2(b2v.x, b2v.y), oB);
        {   const float2* r4 = reinterpret_cast<const float2*>(xc + 288);
            a0 = r4[0]; a1 = r4[1]; a2 = r4[2]; }
        oA = ffma2(kaA[10], pack2(a0.x, a0.y), oA);
        oB = ffma2(kaB[10], pack2(a0.y, a1.x), oB);
        oA = ffma2(kaA[11], pack2(a1.x, a1.y), oA);
        oB = ffma2(kaB[11], pack2(a1.y, a2.x), oB);
        oA = ffma2(kaA[12], pack2(a2.x, a2.x), oA);
        oB = ffma2(kaB[12], pack2(a2.y, a2.y), oB);

        float2 fa = unpack2(oA);
        float2 fb = unpack2(oB);
        float2 rv;
        rv.x = fa.x + fa.y;
        rv.y = fb.x + fb.y;
        *reinterpret_cast<float2*>(
            out + ((size_t)b * CIN + g * GCH + c) * HWPX + px0 + rr * WIDTH + col) = rv;
    }
}

// ---------------------------------------------------------------------------
extern "C" void kernel_launch(void* const* d_in, const int* in_sizes, int n_in,
                              void* d_out, int out_size)
{
    const float* x   = (const float*)d_in[0];
    const float* w1  = (const float*)d_in[1];
    const float* b1  = (const float*)d_in[2];
    const float* gma = (const float*)d_in[3];
    const float* bta = (const float*)d_in[4];
    const float* mu  = (const float*)d_in[5];
    const float* var = (const float*)d_in[6];
    const float* w2  = (const float*)d_in[7];
    const float* b2  = (const float*)d_in[8];
    float* out = (float*)d_out;

    const int SMEM1 = 65536;          // w1t
    const int SMEM2 = 27648 + 7168;   // 34816 B
    cudaFuncSetAttribute(k1_conv1, cudaFuncAttributeMaxDynamicSharedMemorySize, SMEM1);
    cudaFuncSetAttribute(k2_fused, cudaFuncAttributeMaxDynamicSharedMemorySize, SMEM2);

    k1_conv1<<<dim3(32, 8), 256, SMEM1>>>(x, w1, b1, gma, bta, mu, var);
    k2_fused<<<dim3(8, 32, 8), 256, SMEM2>>>(x, w2, b2, out);
}